// round 3
// baseline (speedup 1.0000x reference)
#include <cuda_runtime.h>
#include <cuda_fp16.h>

// LNCC loss, two-pass separable, shuffle-based W window:
//   pass1: warp-shuffle tree 9-tap W sums of {x,y,x2,y2,xy} (packed f32x2),
//          per-thread register sliding 9-tap H sums, -> fp16 scratch.
//          No shared memory, no __syncthreads in the hot loop.
//   pass2: 9-tap D register sliding window per (h,w) + NCC + global reduce.

#define BB 2
#define DD 160
#define HH 160
#define WW 160
#define VOLSZ (DD*HH*WW)
#define VOL2  (BB*VOLSZ)

#define NH 2
#define HS (HH/NH)          // 80 output rows per block
#define ROWS (HS + 8)       // 88 steps

#define ND 2
#define DS (DD/ND)          // 80
#define STEPS (DS + 8)      // 88

#define P1_WARPS 7
#define P1_THREADS (P1_WARPS * 32)   // 224
#define COLS_PER_WARP 24

__device__ __half2 g_scrA[VOL2];   // (Sx,  Sy)
__device__ __half2 g_scrB[VOL2];   // (Sxx, Syy)
__device__ __half  g_scrC[VOL2];   // Sxy
__device__ double  g_acc;

__global__ void zero_acc_kernel() { g_acc = 0.0; }

__global__ void finalize_kernel(float* out) {
    out[0] = (float)(-g_acc * (1.0 / (double)VOL2));
}

// ---- packed f32x2 helpers (sm_100+) ----
typedef unsigned long long ull;
__device__ __forceinline__ ull pk2(float a, float b) {
    ull r; asm("mov.b64 %0, {%1, %2};" : "=l"(r) : "f"(a), "f"(b)); return r;
}
__device__ __forceinline__ void upk2(ull v, float& a, float& b) {
    asm("mov.b64 {%0, %1}, %2;" : "=f"(a), "=f"(b) : "l"(v));
}
__device__ __forceinline__ ull add2(ull a, ull b) {
    ull d; asm("add.rn.f32x2 %0, %1, %2;" : "=l"(d) : "l"(a), "l"(b)); return d;
}
__device__ __forceinline__ ull sub2(ull a, ull b) {
    ull d; asm("sub.rn.f32x2 %0, %1, %2;" : "=l"(d) : "l"(a), "l"(b)); return d;
}
__device__ __forceinline__ ull mul2(ull a, ull b) {
    ull d; asm("mul.rn.f32x2 %0, %1, %2;" : "=l"(d) : "l"(a), "l"(b)); return d;
}

__device__ __forceinline__ int iclamp(int v, int hi) { return min(max(v, 0), hi); }

// 9-tap down-window sum via shuffle tree: result_l = sum(v_l .. v_{l+8})
__device__ __forceinline__ ull wsum9_p(ull v) {
    ull a = add2(v, __shfl_down_sync(0xffffffffu, v, 1));
    ull b = add2(a, __shfl_down_sync(0xffffffffu, a, 2));
    ull c = add2(b, __shfl_down_sync(0xffffffffu, b, 4));
    return add2(c, __shfl_down_sync(0xffffffffu, v, 8));
}
__device__ __forceinline__ float wsum9_s(float v) {
    float a = v + __shfl_down_sync(0xffffffffu, v, 1);
    float b = a + __shfl_down_sync(0xffffffffu, a, 2);
    float c = b + __shfl_down_sync(0xffffffffu, b, 4);
    return c + __shfl_down_sync(0xffffffffu, v, 8);
}

// ================= pass 1 =================
__global__ __launch_bounds__(P1_THREADS)
void lncc_pass1(const float* __restrict__ x, const float* __restrict__ y) {
    const int tid  = threadIdx.x;
    const int wid  = tid >> 5;          // 0..6
    const int lane = tid & 31;

    const int strip = blockIdx.x;
    const int d     = blockIdx.y;
    const int b     = blockIdx.z;
    const int hs0   = strip * HS;

    const int col_out = wid * COLS_PER_WARP + lane;           // center column
    const int col_in  = iclamp(wid * COLS_PER_WARP - 4 + lane, WW - 1);
    const bool emit_w = (lane < COLS_PER_WARP) && (col_out < WW);

    const float* xp = x + ((size_t)b * DD + d) * (HH * WW);
    const float* yp = y + ((size_t)b * DD + d) * (HH * WW);

    ull  h01[9], h23[9];
    float hxy[9];
    #pragma unroll
    for (int k = 0; k < 9; ++k) { h01[k] = 0ull; h23[k] = 0ull; hxy[k] = 0.f; }
    ull run01 = 0ull, run23 = 0ull;
    float runxy = 0.f;

    const size_t obase = ((size_t)b * DD + d) * (HH * WW) + col_out;

    for (int grp = 0; grp < 10; ++grp) {
        #pragma unroll
        for (int k = 0; k < 9; ++k) {
            const int ih = grp * 9 + k;
            if (ih < ROWS) {
                const int gh = iclamp(hs0 - 4 + ih, HH - 1);
                const int off = gh * WW + col_in;
                const float xv = __ldg(xp + off);
                const float yv = __ldg(yp + off);

                const ull p01 = pk2(xv, yv);
                const ull p23 = mul2(p01, p01);
                const float pxy = xv * yv;

                const ull  s01 = wsum9_p(p01);   // (Sx, Sy)   over 9 cols
                const ull  s23 = wsum9_p(p23);   // (Sxx, Syy)
                const float sxy = wsum9_s(pxy);  // Sxy

                // H sliding window (static register slots)
                run01 = add2(run01, sub2(s01, h01[k]));  h01[k] = s01;
                run23 = add2(run23, sub2(s23, h23[k]));  h23[k] = s23;
                runxy += sxy - hxy[k];                   hxy[k] = sxy;

                if (ih >= 8 && emit_w) {
                    float a0, a1, b0, b1;
                    upk2(run01, a0, a1);
                    upk2(run23, b0, b1);
                    const size_t o = obase + (size_t)(hs0 + ih - 8) * WW;
                    g_scrA[o] = __floats2half2_rn(a0, a1);
                    g_scrB[o] = __floats2half2_rn(b0, b1);
                    g_scrC[o] = __float2half_rn(runxy);
                }
            }
        }
    }
}

// ================= pass 2: D sliding + NCC + reduction =================
__global__ __launch_bounds__(160)
void lncc_pass2() {
    const int tx = threadIdx.x;          // w
    const int h  = blockIdx.x;
    const int dc = blockIdx.y;
    const int b  = blockIdx.z;
    const int d0 = dc * DS;

    ull  h01[9], h23[9];
    float hxy[9];
    #pragma unroll
    for (int k = 0; k < 9; ++k) { h01[k] = 0ull; h23[k] = 0ull; hxy[k] = 0.f; }
    ull run01 = 0ull, run23 = 0ull;
    float runxy = 0.f;
    float acc = 0.f;

    const size_t base = ((size_t)b * DD) * (HH * WW) + (size_t)h * WW + tx;
    const float invn = 1.0f / 729.0f;

    for (int grp = 0; grp < 10; ++grp) {
        #pragma unroll
        for (int k = 0; k < 9; ++k) {
            const int jd = grp * 9 + k;
            if (jd < STEPS) {
                const int gd = iclamp(d0 - 4 + jd, DD - 1);
                const size_t idx = base + (size_t)gd * (HH * WW);
                const float2 a = __half22float2(__ldg(&g_scrA[idx]));
                const float2 q = __half22float2(__ldg(&g_scrB[idx]));
                const float  c = __half2float(__ldg(&g_scrC[idx]));

                const ull s01 = pk2(a.x, a.y);
                const ull s23 = pk2(q.x, q.y);
                run01 = add2(run01, sub2(s01, h01[k]));  h01[k] = s01;
                run23 = add2(run23, sub2(s23, h23[k]));  h23[k] = s23;
                runxy += c - hxy[k];                     hxy[k] = c;

                if (jd >= 8) {
                    float sx, sy, sxx, syy;
                    upk2(run01, sx, sy);
                    upk2(run23, sxx, syy);
                    const float xm = sx * invn;
                    const float ym = sy * invn;
                    const float cross = fmaf(-xm, ym, runxy * invn);
                    const float vx    = fmaf(-xm, xm, sxx * invn);
                    const float vy    = fmaf(-ym, ym, syy * invn);
                    acc += __fdividef(cross * cross, fmaf(vx, vy, 1e-5f));
                }
            }
        }
    }

    // block reduce (5 warps) -> double atomic
    __shared__ float red[5];
    #pragma unroll
    for (int o = 16; o > 0; o >>= 1)
        acc += __shfl_down_sync(0xffffffffu, acc, o);
    const int warp = tx >> 5;
    const int lane = tx & 31;
    if (lane == 0) red[warp] = acc;
    __syncthreads();
    if (warp == 0) {
        float v = (lane < 5) ? red[lane] : 0.0f;
        #pragma unroll
        for (int o = 4; o > 0; o >>= 1)
            v += __shfl_down_sync(0xffffffffu, v, o);
        if (lane == 0) atomicAdd(&g_acc, (double)v);
    }
}

extern "C" void kernel_launch(void* const* d_in, const int* in_sizes, int n_in,
                              void* d_out, int out_size) {
    const float* x = (const float*)d_in[0];
    const float* y = (const float*)d_in[1];
    float* out = (float*)d_out;

    zero_acc_kernel<<<1, 1>>>();

    dim3 g1(NH, DD, BB);          // 2 x 160 x 2 = 640 blocks, 224 thr
    lncc_pass1<<<g1, P1_THREADS>>>(x, y);

    dim3 g2(HH, ND, BB);          // 160 x 2 x 2 = 640 blocks, 160 thr
    lncc_pass2<<<g2, 160>>>();

    finalize_kernel<<<1, 1>>>(out);
}

// round 4
// speedup vs baseline: 1.6666x; 1.6666x over previous
#include <cuda_runtime.h>
#include <cuda_fp16.h>

// LNCC loss, two-pass separable:
//   pass1: per (b, d, h-strip): cp.async depth-3 row pipeline -> smem raw row,
//          direct 9-tap W sums (packed f32x2), 9-tap H sums via per-thread
//          static register sliding window -> fp16 scratch. 1 sync/row.
//   pass2: 9-tap D register sliding window per (h,w) + NCC + global reduce,
//          with fused finalize (atomic ticket).

#define BB 2
#define DD 160
#define HH 160
#define WW 160
#define VOLSZ (DD*HH*WW)
#define VOL2  (BB*VOLSZ)

#define NH 4
#define HS (HH/NH)          // 40 output rows per block
#define ROWS (HS + 8)       // 48 row steps

#define ND 4
#define DS (DD/ND)          // 40
#define STEPS (DS + 8)      // 48

#define P2_BLOCKS (HH * ND * BB)   // 1280

__device__ __half2 g_scrA[VOL2];   // (Sx,  Sy)
__device__ __half2 g_scrB[VOL2];   // (Sxx, Syy)
__device__ __half  g_scrC[VOL2];   // Sxy
__device__ double  g_acc;
__device__ unsigned int g_ctr;

// ---- packed f32x2 helpers (sm_100+) ----
typedef unsigned long long ull;
__device__ __forceinline__ ull pk2(float a, float b) {
    ull r; asm("mov.b64 %0, {%1, %2};" : "=l"(r) : "f"(a), "f"(b)); return r;
}
__device__ __forceinline__ void upk2(ull v, float& a, float& b) {
    asm("mov.b64 {%0, %1}, %2;" : "=f"(a), "=f"(b) : "l"(v));
}
__device__ __forceinline__ ull add2(ull a, ull b) {
    ull d; asm("add.rn.f32x2 %0, %1, %2;" : "=l"(d) : "l"(a), "l"(b)); return d;
}
__device__ __forceinline__ ull sub2(ull a, ull b) {
    ull d; asm("sub.rn.f32x2 %0, %1, %2;" : "=l"(d) : "l"(a), "l"(b)); return d;
}
__device__ __forceinline__ ull fma2(ull a, ull b, ull c) {
    ull d; asm("fma.rn.f32x2 %0, %1, %2, %3;" : "=l"(d) : "l"(a), "l"(b), "l"(c)); return d;
}

__device__ __forceinline__ int iclamp(int v, int hi) { return min(max(v, 0), hi); }

__device__ __forceinline__ void cpa4(void* dst_smem, const void* src) {
    unsigned s = (unsigned)__cvta_generic_to_shared(dst_smem);
    asm volatile("cp.async.ca.shared.global [%0], [%1], 4;" :: "r"(s), "l"(src));
}
#define CPA_COMMIT() asm volatile("cp.async.commit_group;" ::: "memory")
#define CPA_WAIT2()  asm volatile("cp.async.wait_group 2;" ::: "memory")

// ================= pass 1 =================
__global__ __launch_bounds__(WW)
void lncc_pass1(const float* __restrict__ x, const float* __restrict__ y) {
    __shared__ float2 buf[4][WW + 8];

    const int tx    = threadIdx.x;       // 0..159 (output column)
    const int strip = blockIdx.x;
    const int d     = blockIdx.y;
    const int b     = blockIdx.z;
    const int hs0   = strip * HS;

    if (blockIdx.x == 0 && blockIdx.y == 0 && blockIdx.z == 0 && tx == 0) {
        g_acc = 0.0;
        g_ctr = 0u;
    }

    const float* xp = x + ((size_t)b * DD + d) * (HH * WW);
    const float* yp = y + ((size_t)b * DD + d) * (HH * WW);

    const int gw  = iclamp(tx - 4, WW - 1);
    const int gw2 = min(156 + tx, WW - 1);      // used when tx < 8

    // issue row ih into buf[ih & 3]
    auto issue = [&](int ih) {
        const int gh = iclamp(hs0 - 4 + ih, HH - 1);
        const float* xr = xp + gh * WW;
        const float* yr = yp + gh * WW;
        float2* dst = buf[ih & 3];
        cpa4(&dst[tx].x, xr + gw);
        cpa4(&dst[tx].y, yr + gw);
        if (tx < 8) {
            cpa4(&dst[WW + tx].x, xr + gw2);
            cpa4(&dst[WW + tx].y, yr + gw2);
        }
        CPA_COMMIT();
    };

    issue(0); issue(1); issue(2);

    ull  h01[9], h23[9];
    float hxy[9];
    #pragma unroll
    for (int k = 0; k < 9; ++k) { h01[k] = 0ull; h23[k] = 0ull; hxy[k] = 0.f; }
    ull run01 = 0ull, run23 = 0ull;
    float runxy = 0.f;

    const size_t obase = ((size_t)b * DD + d) * (HH * WW) + tx;

    #pragma unroll
    for (int ih = 0; ih < ROWS; ++ih) {
        CPA_WAIT2();            // row ih complete (<=2 newest groups pending)
        __syncthreads();        // everyone done with row ih-1, data for ih visible

        if (ih + 3 < ROWS) issue(ih + 3);
        else               CPA_COMMIT();   // keep group accounting uniform

        const float2* row = buf[ih & 3];
        ull s01 = 0ull, s23 = 0ull;
        float sxy = 0.f;
        #pragma unroll
        for (int t = 0; t < 9; ++t) {
            const float2 p = row[tx + t];
            const ull pp = pk2(p.x, p.y);
            s01 = add2(s01, pp);
            s23 = fma2(pp, pp, s23);
            sxy = fmaf(p.x, p.y, sxy);
        }

        const int k = ih % 9;   // static per unrolled iteration
        run01 = add2(run01, sub2(s01, h01[k]));  h01[k] = s01;
        run23 = add2(run23, sub2(s23, h23[k]));  h23[k] = s23;
        runxy += sxy - hxy[k];                   hxy[k] = sxy;

        if (ih >= 8) {
            float a0, a1, b0, b1;
            upk2(run01, a0, a1);
            upk2(run23, b0, b1);
            const size_t o = obase + (size_t)(hs0 + ih - 8) * WW;
            g_scrA[o] = __floats2half2_rn(a0, a1);
            g_scrB[o] = __floats2half2_rn(b0, b1);
            g_scrC[o] = __float2half_rn(runxy);
        }
    }
}

// ================= pass 2: D sliding + NCC + reduction + finalize ============
__global__ __launch_bounds__(WW)
void lncc_pass2(float* __restrict__ out) {
    const int tx = threadIdx.x;          // w
    const int h  = blockIdx.x;
    const int dc = blockIdx.y;
    const int b  = blockIdx.z;
    const int d0 = dc * DS;

    ull  h01[9], h23[9];
    float hxy[9];
    #pragma unroll
    for (int k = 0; k < 9; ++k) { h01[k] = 0ull; h23[k] = 0ull; hxy[k] = 0.f; }
    ull run01 = 0ull, run23 = 0ull;
    float runxy = 0.f;
    float acc = 0.f;

    const size_t base = ((size_t)b * DD) * (HH * WW) + (size_t)h * WW + tx;
    const float invn = 1.0f / 729.0f;

    #pragma unroll
    for (int jd = 0; jd < STEPS; ++jd) {
        const int gd = iclamp(d0 - 4 + jd, DD - 1);
        const size_t idx = base + (size_t)gd * (HH * WW);
        const float2 a = __half22float2(__ldg(&g_scrA[idx]));
        const float2 q = __half22float2(__ldg(&g_scrB[idx]));
        const float  c = __half2float(__ldg(&g_scrC[idx]));

        const int k = jd % 9;            // static per unrolled iteration
        const ull s01 = pk2(a.x, a.y);
        const ull s23 = pk2(q.x, q.y);
        run01 = add2(run01, sub2(s01, h01[k]));  h01[k] = s01;
        run23 = add2(run23, sub2(s23, h23[k]));  h23[k] = s23;
        runxy += c - hxy[k];                     hxy[k] = c;

        if (jd >= 8) {
            float sx, sy, sxx, syy;
            upk2(run01, sx, sy);
            upk2(run23, sxx, syy);
            const float xm = sx * invn;
            const float ym = sy * invn;
            const float cross = fmaf(-xm, ym, runxy * invn);
            const float vx    = fmaf(-xm, xm, sxx * invn);
            const float vy    = fmaf(-ym, ym, syy * invn);
            acc += __fdividef(cross * cross, fmaf(vx, vy, 1e-5f));
        }
    }

    // block reduce (5 warps) -> double atomic -> fused finalize
    __shared__ float red[5];
    #pragma unroll
    for (int o = 16; o > 0; o >>= 1)
        acc += __shfl_down_sync(0xffffffffu, acc, o);
    const int warp = tx >> 5;
    const int lane = tx & 31;
    if (lane == 0) red[warp] = acc;
    __syncthreads();
    if (warp == 0 && lane == 0) {
        float v = red[0] + red[1] + red[2] + red[3] + red[4];
        atomicAdd(&g_acc, (double)v);
        __threadfence();
        const unsigned ticket = atomicAdd(&g_ctr, 1u);
        if (ticket == (unsigned)(P2_BLOCKS - 1)) {
            double total = atomicAdd(&g_acc, 0.0);   // ordered read
            out[0] = (float)(-total * (1.0 / (double)VOL2));
        }
    }
}

extern "C" void kernel_launch(void* const* d_in, const int* in_sizes, int n_in,
                              void* d_out, int out_size) {
    (void)in_sizes; (void)n_in; (void)out_size;
    const float* x = (const float*)d_in[0];
    const float* y = (const float*)d_in[1];
    float* out = (float*)d_out;

    dim3 g1(NH, DD, BB);          // 4 x 160 x 2 = 1280 blocks, 160 thr
    lncc_pass1<<<g1, WW>>>(x, y);

    dim3 g2(HH, ND, BB);          // 160 x 4 x 2 = 1280 blocks, 160 thr
    lncc_pass2<<<g2, WW>>>(out);
}

// round 5
// speedup vs baseline: 1.9470x; 1.1682x over previous
#include <cuda_runtime.h>
#include <cuda_fp16.h>

// LNCC loss, two-pass separable:
//   pass1: cp.async row pipeline -> smem, 9-tap W sums (packed f32x2),
//          9-tap H register sliding window -> ONE 16B scratch record/voxel.
//   pass2: 9-tap D sliding window, one LDG.128/step with 4-deep register
//          prefetch, fp16-bit history, NCC + fused reduction/finalize.

#define BB 2
#define DD 160
#define HH 160
#define WW 160
#define VOLSZ (DD*HH*WW)
#define VOL2  (BB*VOLSZ)

#define NH 4
#define HS (HH/NH)          // 40 output rows per block
#define ROWS (HS + 8)       // 48 row steps

#define ND 4
#define DS (DD/ND)          // 40
#define STEPS (DS + 8)      // 48

#define P2_BLOCKS (HH * ND * BB)   // 1280

__device__ uint4  g_scr[VOL2];     // {half2(Sx,Sy), half2(Sxx,Syy), half(Sxy), pad}
__device__ double g_acc;
__device__ unsigned int g_ctr;

// ---- packed f32x2 helpers (sm_100+) ----
typedef unsigned long long ull;
__device__ __forceinline__ ull pk2(float a, float b) {
    ull r; asm("mov.b64 %0, {%1, %2};" : "=l"(r) : "f"(a), "f"(b)); return r;
}
__device__ __forceinline__ void upk2(ull v, float& a, float& b) {
    asm("mov.b64 {%0, %1}, %2;" : "=f"(a), "=f"(b) : "l"(v));
}
__device__ __forceinline__ ull add2(ull a, ull b) {
    ull d; asm("add.rn.f32x2 %0, %1, %2;" : "=l"(d) : "l"(a), "l"(b)); return d;
}
__device__ __forceinline__ ull sub2(ull a, ull b) {
    ull d; asm("sub.rn.f32x2 %0, %1, %2;" : "=l"(d) : "l"(a), "l"(b)); return d;
}
__device__ __forceinline__ ull fma2(ull a, ull b, ull c) {
    ull d; asm("fma.rn.f32x2 %0, %1, %2, %3;" : "=l"(d) : "l"(a), "l"(b), "l"(c)); return d;
}

__device__ __forceinline__ int iclamp(int v, int hi) { return min(max(v, 0), hi); }

__device__ __forceinline__ float2 h2f(unsigned bits) {
    __half2 h = *reinterpret_cast<__half2*>(&bits);
    return __half22float2(h);
}
__device__ __forceinline__ float h1f(unsigned bits) {
    unsigned short s = (unsigned short)bits;
    __half h = *reinterpret_cast<__half*>(&s);
    return __half2float(h);
}

__device__ __forceinline__ void cpa4(void* dst_smem, const void* src) {
    unsigned s = (unsigned)__cvta_generic_to_shared(dst_smem);
    asm volatile("cp.async.ca.shared.global [%0], [%1], 4;" :: "r"(s), "l"(src));
}
#define CPA_COMMIT() asm volatile("cp.async.commit_group;" ::: "memory")
#define CPA_WAIT2()  asm volatile("cp.async.wait_group 2;" ::: "memory")

// ================= pass 1 =================
__global__ __launch_bounds__(WW)
void lncc_pass1(const float* __restrict__ x, const float* __restrict__ y) {
    __shared__ float2 buf[4][WW + 8];

    const int tx    = threadIdx.x;       // 0..159 (output column)
    const int strip = blockIdx.x;
    const int d     = blockIdx.y;
    const int b     = blockIdx.z;
    const int hs0   = strip * HS;

    if (blockIdx.x == 0 && blockIdx.y == 0 && blockIdx.z == 0 && tx == 0) {
        g_acc = 0.0;
        g_ctr = 0u;
    }

    const float* xp = x + ((size_t)b * DD + d) * (HH * WW);
    const float* yp = y + ((size_t)b * DD + d) * (HH * WW);

    const int gw  = iclamp(tx - 4, WW - 1);
    const int gw2 = min(156 + tx, WW - 1);      // used when tx < 8

    auto issue = [&](int ih) {
        const int gh = iclamp(hs0 - 4 + ih, HH - 1);
        const float* xr = xp + gh * WW;
        const float* yr = yp + gh * WW;
        float2* dst = buf[ih & 3];
        cpa4(&dst[tx].x, xr + gw);
        cpa4(&dst[tx].y, yr + gw);
        if (tx < 8) {
            cpa4(&dst[WW + tx].x, xr + gw2);
            cpa4(&dst[WW + tx].y, yr + gw2);
        }
        CPA_COMMIT();
    };

    issue(0); issue(1); issue(2);

    ull  h01[9], h23[9];
    float hxy[9];
    #pragma unroll
    for (int k = 0; k < 9; ++k) { h01[k] = 0ull; h23[k] = 0ull; hxy[k] = 0.f; }
    ull run01 = 0ull, run23 = 0ull;
    float runxy = 0.f;

    const size_t obase = ((size_t)b * DD + d) * (HH * WW) + tx;

    #pragma unroll
    for (int ih = 0; ih < ROWS; ++ih) {
        CPA_WAIT2();
        __syncthreads();

        if (ih + 3 < ROWS) issue(ih + 3);
        else               CPA_COMMIT();

        const float2* row = buf[ih & 3];
        ull s01 = 0ull, s23 = 0ull;
        float sxy = 0.f;
        #pragma unroll
        for (int t = 0; t < 9; ++t) {
            const float2 p = row[tx + t];
            const ull pp = pk2(p.x, p.y);
            s01 = add2(s01, pp);
            s23 = fma2(pp, pp, s23);
            sxy = fmaf(p.x, p.y, sxy);
        }

        const int k = ih % 9;
        run01 = add2(run01, sub2(s01, h01[k]));  h01[k] = s01;
        run23 = add2(run23, sub2(s23, h23[k]));  h23[k] = s23;
        runxy += sxy - hxy[k];                   hxy[k] = sxy;

        if (ih >= 8) {
            float a0, a1, b0, b1;
            upk2(run01, a0, a1);
            upk2(run23, b0, b1);
            __half2 ha = __floats2half2_rn(a0, a1);
            __half2 hb = __floats2half2_rn(b0, b1);
            __half  hc = __float2half_rn(runxy);
            unsigned short cs = *reinterpret_cast<unsigned short*>(&hc);
            uint4 rec;
            rec.x = *reinterpret_cast<unsigned*>(&ha);
            rec.y = *reinterpret_cast<unsigned*>(&hb);
            rec.z = (unsigned)cs;
            rec.w = 0u;
            const size_t o = obase + (size_t)(hs0 + ih - 8) * WW;
            g_scr[o] = rec;
        }
    }
}

// ================= pass 2: D sliding + NCC + reduction + finalize ============
__global__ __launch_bounds__(WW)
void lncc_pass2(float* __restrict__ out) {
    const int tx = threadIdx.x;          // w
    const int h  = blockIdx.x;
    const int dc = blockIdx.y;
    const int b  = blockIdx.z;
    const int d0 = dc * DS;

    const size_t base = ((size_t)b * DD) * (HH * WW) + (size_t)h * WW + tx;

    auto addr = [&](int jd) -> const uint4* {
        const int gd = iclamp(d0 - 4 + jd, DD - 1);
        return &g_scr[base + (size_t)gd * (HH * WW)];
    };

    // 4-deep prefetch pipeline
    uint4 pipe[4];
    #pragma unroll
    for (int i = 0; i < 4; ++i) pipe[i] = __ldg(addr(i));

    // history kept as raw fp16 bits (exact add/sub round trip)
    unsigned hx[9], hy[9], hz[9];
    #pragma unroll
    for (int k = 0; k < 9; ++k) { hx[k] = 0u; hy[k] = 0u; hz[k] = 0u; }
    ull run01 = 0ull, run23 = 0ull;
    float runxy = 0.f;
    float acc = 0.f;

    const float invn = 1.0f / 729.0f;

    #pragma unroll
    for (int jd = 0; jd < STEPS; ++jd) {
        const uint4 rec = pipe[jd & 3];
        if (jd + 4 < STEPS) pipe[jd & 3] = __ldg(addr(jd + 4));

        const int k = jd % 9;
        const float2 a  = h2f(rec.x);
        const float2 q  = h2f(rec.y);
        const float  c  = h1f(rec.z);
        const float2 oa = h2f(hx[k]);
        const float2 oq = h2f(hy[k]);
        const float  oc = h1f(hz[k]);
        hx[k] = rec.x; hy[k] = rec.y; hz[k] = rec.z;

        run01 = add2(run01, sub2(pk2(a.x, a.y), pk2(oa.x, oa.y)));
        run23 = add2(run23, sub2(pk2(q.x, q.y), pk2(oq.x, oq.y)));
        runxy += c - oc;

        if (jd >= 8) {
            float sx, sy, sxx, syy;
            upk2(run01, sx, sy);
            upk2(run23, sxx, syy);
            const float xm = sx * invn;
            const float ym = sy * invn;
            const float cross = fmaf(-xm, ym, runxy * invn);
            const float vx    = fmaf(-xm, xm, sxx * invn);
            const float vy    = fmaf(-ym, ym, syy * invn);
            acc += __fdividef(cross * cross, fmaf(vx, vy, 1e-5f));
        }
    }

    // block reduce (5 warps) -> double atomic -> fused finalize
    __shared__ float red[5];
    #pragma unroll
    for (int o = 16; o > 0; o >>= 1)
        acc += __shfl_down_sync(0xffffffffu, acc, o);
    const int warp = tx >> 5;
    const int lane = tx & 31;
    if (lane == 0) red[warp] = acc;
    __syncthreads();
    if (warp == 0 && lane == 0) {
        float v = red[0] + red[1] + red[2] + red[3] + red[4];
        atomicAdd(&g_acc, (double)v);
        __threadfence();
        const unsigned ticket = atomicAdd(&g_ctr, 1u);
        if (ticket == (unsigned)(P2_BLOCKS - 1)) {
            double total = atomicAdd(&g_acc, 0.0);   // ordered read
            out[0] = (float)(-total * (1.0 / (double)VOL2));
        }
    }
}

extern "C" void kernel_launch(void* const* d_in, const int* in_sizes, int n_in,
                              void* d_out, int out_size) {
    (void)in_sizes; (void)n_in; (void)out_size;
    const float* x = (const float*)d_in[0];
    const float* y = (const float*)d_in[1];
    float* out = (float*)d_out;

    dim3 g1(NH, DD, BB);          // 4 x 160 x 2 = 1280 blocks, 160 thr
    lncc_pass1<<<g1, WW>>>(x, y);

    dim3 g2(HH, ND, BB);          // 160 x 4 x 2 = 1280 blocks, 160 thr
    lncc_pass2<<<g2, WW>>>(out);
}

// round 6
// speedup vs baseline: 1.9893x; 1.0217x over previous
#include <cuda_runtime.h>
#include <cuda_fp16.h>

// LNCC loss, two-pass separable:
//   pass1: cp.async row pipeline -> smem, 9-tap W sums (packed f32x2),
//          9-tap H register sliding window -> 10 B/voxel fp16 scratch
//          (uint2 {Sx,Sy,Sxx,Syy} + ushort {Sxy}).
//   pass2: 9-tap D sliding window, depth-4 register prefetch, fp16-bit
//          history, NCC + fused reduction/finalize.

#define BB 2
#define DD 160
#define HH 160
#define WW 160
#define VOLSZ (DD*HH*WW)
#define VOL2  (BB*VOLSZ)

#define NH 4
#define HS (HH/NH)          // 40 output rows per block
#define ROWS (HS + 8)       // 48 row steps

#define ND 4
#define DS (DD/ND)          // 40
#define STEPS (DS + 8)      // 48

#define P2_BLOCKS (HH * ND * BB)   // 1280

__device__ uint2          g_scrA[VOL2];   // {half2(Sx,Sy), half2(Sxx,Syy)}
__device__ unsigned short g_scrC[VOL2];   // half(Sxy)
__device__ double g_acc;
__device__ unsigned int g_ctr;

// ---- packed f32x2 helpers (sm_100+) ----
typedef unsigned long long ull;
__device__ __forceinline__ ull pk2(float a, float b) {
    ull r; asm("mov.b64 %0, {%1, %2};" : "=l"(r) : "f"(a), "f"(b)); return r;
}
__device__ __forceinline__ void upk2(ull v, float& a, float& b) {
    asm("mov.b64 {%0, %1}, %2;" : "=f"(a), "=f"(b) : "l"(v));
}
__device__ __forceinline__ ull add2(ull a, ull b) {
    ull d; asm("add.rn.f32x2 %0, %1, %2;" : "=l"(d) : "l"(a), "l"(b)); return d;
}
__device__ __forceinline__ ull sub2(ull a, ull b) {
    ull d; asm("sub.rn.f32x2 %0, %1, %2;" : "=l"(d) : "l"(a), "l"(b)); return d;
}
__device__ __forceinline__ ull fma2(ull a, ull b, ull c) {
    ull d; asm("fma.rn.f32x2 %0, %1, %2, %3;" : "=l"(d) : "l"(a), "l"(b), "l"(c)); return d;
}

__device__ __forceinline__ int iclamp(int v, int hi) { return min(max(v, 0), hi); }

__device__ __forceinline__ float2 h2f(unsigned bits) {
    __half2 h = *reinterpret_cast<__half2*>(&bits);
    return __half22float2(h);
}
__device__ __forceinline__ float h1f(unsigned short bits) {
    __half h = *reinterpret_cast<__half*>(&bits);
    return __half2float(h);
}

__device__ __forceinline__ void cpa4(void* dst_smem, const void* src) {
    unsigned s = (unsigned)__cvta_generic_to_shared(dst_smem);
    asm volatile("cp.async.ca.shared.global [%0], [%1], 4;" :: "r"(s), "l"(src));
}
#define CPA_COMMIT() asm volatile("cp.async.commit_group;" ::: "memory")
#define CPA_WAIT2()  asm volatile("cp.async.wait_group 2;" ::: "memory")

// ================= pass 1 =================
__global__ __launch_bounds__(WW)
void lncc_pass1(const float* __restrict__ x, const float* __restrict__ y) {
    __shared__ float2 buf[4][WW + 8];

    const int tx    = threadIdx.x;       // 0..159 (output column)
    const int strip = blockIdx.x;
    const int d     = blockIdx.y;
    const int b     = blockIdx.z;
    const int hs0   = strip * HS;

    if (blockIdx.x == 0 && blockIdx.y == 0 && blockIdx.z == 0 && tx == 0) {
        g_acc = 0.0;
        g_ctr = 0u;
    }

    const float* xp = x + ((size_t)b * DD + d) * (HH * WW);
    const float* yp = y + ((size_t)b * DD + d) * (HH * WW);

    const int gw  = iclamp(tx - 4, WW - 1);
    const int gw2 = min(156 + tx, WW - 1);      // used when tx < 8

    auto issue = [&](int ih) {
        const int gh = iclamp(hs0 - 4 + ih, HH - 1);
        const float* xr = xp + gh * WW;
        const float* yr = yp + gh * WW;
        float2* dst = buf[ih & 3];
        cpa4(&dst[tx].x, xr + gw);
        cpa4(&dst[tx].y, yr + gw);
        if (tx < 8) {
            cpa4(&dst[WW + tx].x, xr + gw2);
            cpa4(&dst[WW + tx].y, yr + gw2);
        }
        CPA_COMMIT();
    };

    issue(0); issue(1); issue(2);

    ull  h01[9], h23[9];
    float hxy[9];
    #pragma unroll
    for (int k = 0; k < 9; ++k) { h01[k] = 0ull; h23[k] = 0ull; hxy[k] = 0.f; }
    ull run01 = 0ull, run23 = 0ull;
    float runxy = 0.f;

    const size_t obase = ((size_t)b * DD + d) * (HH * WW) + tx;

    #pragma unroll
    for (int ih = 0; ih < ROWS; ++ih) {
        CPA_WAIT2();
        __syncthreads();

        if (ih + 3 < ROWS) issue(ih + 3);
        else               CPA_COMMIT();

        const float2* row = buf[ih & 3];
        ull s01 = 0ull, s23 = 0ull;
        float sxy = 0.f;
        #pragma unroll
        for (int t = 0; t < 9; ++t) {
            const float2 p = row[tx + t];
            const ull pp = pk2(p.x, p.y);
            s01 = add2(s01, pp);
            s23 = fma2(pp, pp, s23);
            sxy = fmaf(p.x, p.y, sxy);
        }

        const int k = ih % 9;
        run01 = add2(run01, sub2(s01, h01[k]));  h01[k] = s01;
        run23 = add2(run23, sub2(s23, h23[k]));  h23[k] = s23;
        runxy += sxy - hxy[k];                   hxy[k] = sxy;

        if (ih >= 8) {
            float a0, a1, b0, b1;
            upk2(run01, a0, a1);
            upk2(run23, b0, b1);
            __half2 ha = __floats2half2_rn(a0, a1);
            __half2 hb = __floats2half2_rn(b0, b1);
            __half  hc = __float2half_rn(runxy);
            uint2 rec;
            rec.x = *reinterpret_cast<unsigned*>(&ha);
            rec.y = *reinterpret_cast<unsigned*>(&hb);
            const size_t o = obase + (size_t)(hs0 + ih - 8) * WW;
            g_scrA[o] = rec;
            g_scrC[o] = *reinterpret_cast<unsigned short*>(&hc);
        }
    }
}

// ================= pass 2: D sliding + NCC + reduction + finalize ============
__global__ __launch_bounds__(WW)
void lncc_pass2(float* __restrict__ out) {
    const int tx = threadIdx.x;          // w
    const int h  = blockIdx.x;
    const int dc = blockIdx.y;
    const int b  = blockIdx.z;
    const int d0 = dc * DS;

    const size_t base = ((size_t)b * DD) * (HH * WW) + (size_t)h * WW + tx;

    auto sidx = [&](int jd) -> size_t {
        const int gd = iclamp(d0 - 4 + jd, DD - 1);
        return base + (size_t)gd * (HH * WW);
    };

    // 4-deep prefetch pipeline
    uint2 pipeA[4];
    unsigned short pipeC[4];
    #pragma unroll
    for (int i = 0; i < 4; ++i) {
        const size_t idx = sidx(i);
        pipeA[i] = __ldg(&g_scrA[idx]);
        pipeC[i] = __ldg(&g_scrC[idx]);
    }

    // history kept as raw fp16 bits (exact add/sub round trip)
    unsigned hx[9], hy[9];
    unsigned short hz[9];
    #pragma unroll
    for (int k = 0; k < 9; ++k) { hx[k] = 0u; hy[k] = 0u; hz[k] = 0; }
    ull run01 = 0ull, run23 = 0ull;
    float runxy = 0.f;
    float acc = 0.f;

    const float invn = 1.0f / 729.0f;

    #pragma unroll
    for (int jd = 0; jd < STEPS; ++jd) {
        const uint2 recA = pipeA[jd & 3];
        const unsigned short recC = pipeC[jd & 3];
        if (jd + 4 < STEPS) {
            const size_t idx = sidx(jd + 4);
            pipeA[jd & 3] = __ldg(&g_scrA[idx]);
            pipeC[jd & 3] = __ldg(&g_scrC[idx]);
        }

        const int k = jd % 9;
        const float2 a  = h2f(recA.x);
        const float2 q  = h2f(recA.y);
        const float  c  = h1f(recC);
        const float2 oa = h2f(hx[k]);
        const float2 oq = h2f(hy[k]);
        const float  oc = h1f(hz[k]);
        hx[k] = recA.x; hy[k] = recA.y; hz[k] = recC;

        run01 = add2(run01, sub2(pk2(a.x, a.y), pk2(oa.x, oa.y)));
        run23 = add2(run23, sub2(pk2(q.x, q.y), pk2(oq.x, oq.y)));
        runxy += c - oc;

        if (jd >= 8) {
            float sx, sy, sxx, syy;
            upk2(run01, sx, sy);
            upk2(run23, sxx, syy);
            const float xm = sx * invn;
            const float ym = sy * invn;
            const float cross = fmaf(-xm, ym, runxy * invn);
            const float vx    = fmaf(-xm, xm, sxx * invn);
            const float vy    = fmaf(-ym, ym, syy * invn);
            acc += __fdividef(cross * cross, fmaf(vx, vy, 1e-5f));
        }
    }

    // block reduce (5 warps) -> double atomic -> fused finalize
    __shared__ float red[5];
    #pragma unroll
    for (int o = 16; o > 0; o >>= 1)
        acc += __shfl_down_sync(0xffffffffu, acc, o);
    const int warp = tx >> 5;
    const int lane = tx & 31;
    if (lane == 0) red[warp] = acc;
    __syncthreads();
    if (warp == 0 && lane == 0) {
        float v = red[0] + red[1] + red[2] + red[3] + red[4];
        atomicAdd(&g_acc, (double)v);
        __threadfence();
        const unsigned ticket = atomicAdd(&g_ctr, 1u);
        if (ticket == (unsigned)(P2_BLOCKS - 1)) {
            double total = atomicAdd(&g_acc, 0.0);   // ordered read
            out[0] = (float)(-total * (1.0 / (double)VOL2));
        }
    }
}

extern "C" void kernel_launch(void* const* d_in, const int* in_sizes, int n_in,
                              void* d_out, int out_size) {
    (void)in_sizes; (void)n_in; (void)out_size;
    const float* x = (const float*)d_in[0];
    const float* y = (const float*)d_in[1];
    float* out = (float*)d_out;

    dim3 g1(NH, DD, BB);          // 4 x 160 x 2 = 1280 blocks, 160 thr
    lncc_pass1<<<g1, WW>>>(x, y);

    dim3 g2(HH, ND, BB);          // 160 x 4 x 2 = 1280 blocks, 160 thr
    lncc_pass2<<<g2, WW>>>(out);
}

// round 7
// speedup vs baseline: 2.3107x; 1.1616x over previous
#include <cuda_runtime.h>
#include <cuda_fp16.h>

// LNCC loss, two-pass separable:
//   pass1: cp.async 8-row ring (prefetch distance 6), 2 rows per barrier,
//          9-tap W sums (packed f32x2), 9-tap H register sliding window
//          -> 10 B/voxel fp16 scratch (uint2 {Sx,Sy,Sxx,Syy} + ushort Sxy).
//   pass2: thread owns 2 adjacent w columns: one LDG.128 + one LDG.32 per
//          D-step, depth-4 register prefetch, fp16-bit history, NCC +
//          fused reduction/finalize.

#define BB 2
#define DD 160
#define HH 160
#define WW 160
#define VOLSZ (DD*HH*WW)
#define VOL2  (BB*VOLSZ)

#define NH 4
#define HS (HH/NH)          // 40 output rows per block
#define ROWS (HS + 8)       // 48 row steps

#define ND 4
#define DS (DD/ND)          // 40
#define STEPS (DS + 8)      // 48

#define P2_BLOCKS ((HH/2) * ND * BB)   // 640

__device__ __align__(16) uint2          g_scrA[VOL2];   // {half2(Sx,Sy), half2(Sxx,Syy)}
__device__ __align__(16) unsigned short g_scrC[VOL2];   // half(Sxy)
__device__ double g_acc;
__device__ unsigned int g_ctr;

// ---- packed f32x2 helpers (sm_100+) ----
typedef unsigned long long ull;
__device__ __forceinline__ ull pk2(float a, float b) {
    ull r; asm("mov.b64 %0, {%1, %2};" : "=l"(r) : "f"(a), "f"(b)); return r;
}
__device__ __forceinline__ void upk2(ull v, float& a, float& b) {
    asm("mov.b64 {%0, %1}, %2;" : "=f"(a), "=f"(b) : "l"(v));
}
__device__ __forceinline__ ull add2(ull a, ull b) {
    ull d; asm("add.rn.f32x2 %0, %1, %2;" : "=l"(d) : "l"(a), "l"(b)); return d;
}
__device__ __forceinline__ ull sub2(ull a, ull b) {
    ull d; asm("sub.rn.f32x2 %0, %1, %2;" : "=l"(d) : "l"(a), "l"(b)); return d;
}
__device__ __forceinline__ ull fma2(ull a, ull b, ull c) {
    ull d; asm("fma.rn.f32x2 %0, %1, %2, %3;" : "=l"(d) : "l"(a), "l"(b), "l"(c)); return d;
}

__device__ __forceinline__ int iclamp(int v, int hi) { return min(max(v, 0), hi); }

__device__ __forceinline__ float2 h2f(unsigned bits) {
    __half2 h = *reinterpret_cast<__half2*>(&bits);
    return __half22float2(h);
}

__device__ __forceinline__ void cpa4(void* dst_smem, const void* src) {
    unsigned s = (unsigned)__cvta_generic_to_shared(dst_smem);
    asm volatile("cp.async.ca.shared.global [%0], [%1], 4;" :: "r"(s), "l"(src));
}
#define CPA_COMMIT() asm volatile("cp.async.commit_group;" ::: "memory")
#define CPA_WAIT4()  asm volatile("cp.async.wait_group 4;" ::: "memory")

// ================= pass 1 =================
__global__ __launch_bounds__(WW)
void lncc_pass1(const float* __restrict__ x, const float* __restrict__ y) {
    __shared__ float2 buf[8][WW + 8];

    const int tx    = threadIdx.x;       // 0..159 (output column)
    const int strip = blockIdx.x;
    const int d     = blockIdx.y;
    const int b     = blockIdx.z;
    const int hs0   = strip * HS;

    if (blockIdx.x == 0 && blockIdx.y == 0 && blockIdx.z == 0 && tx == 0) {
        g_acc = 0.0;
        g_ctr = 0u;
    }

    const float* xp = x + ((size_t)b * DD + d) * (HH * WW);
    const float* yp = y + ((size_t)b * DD + d) * (HH * WW);

    const int gw  = iclamp(tx - 4, WW - 1);
    const int gw2 = min(156 + tx, WW - 1);      // used when tx < 8

    auto issue = [&](int r) {
        const int gh = iclamp(hs0 - 4 + r, HH - 1);
        const float* xr = xp + gh * WW;
        const float* yr = yp + gh * WW;
        float2* dst = buf[r & 7];
        cpa4(&dst[tx].x, xr + gw);
        cpa4(&dst[tx].y, yr + gw);
        if (tx < 8) {
            cpa4(&dst[WW + tx].x, xr + gw2);
            cpa4(&dst[WW + tx].y, yr + gw2);
        }
        CPA_COMMIT();
    };

    issue(0); issue(1); issue(2); issue(3); issue(4); issue(5);

    ull  h01[9], h23[9];
    float hxy[9];
    #pragma unroll
    for (int k = 0; k < 9; ++k) { h01[k] = 0ull; h23[k] = 0ull; hxy[k] = 0.f; }
    ull run01 = 0ull, run23 = 0ull;
    float runxy = 0.f;

    const size_t obase = ((size_t)b * DD + d) * (HH * WW) + tx;

    #pragma unroll
    for (int it = 0; it < ROWS / 2; ++it) {
        CPA_WAIT4();            // rows 2it, 2it+1 landed (<=4 newer groups pending)
        __syncthreads();

        if (2 * it + 6 < ROWS) issue(2 * it + 6);
        if (2 * it + 7 < ROWS) issue(2 * it + 7);

        #pragma unroll
        for (int sub = 0; sub < 2; ++sub) {
            const int r = 2 * it + sub;
            const float2* row = buf[r & 7];

            ull s01 = 0ull, s23 = 0ull;
            float sxy = 0.f;
            #pragma unroll
            for (int t = 0; t < 9; ++t) {
                const float2 p = row[tx + t];
                const ull pp = pk2(p.x, p.y);
                s01 = add2(s01, pp);
                s23 = fma2(pp, pp, s23);
                sxy = fmaf(p.x, p.y, sxy);
            }

            const int k = r % 9;
            run01 = add2(run01, sub2(s01, h01[k]));  h01[k] = s01;
            run23 = add2(run23, sub2(s23, h23[k]));  h23[k] = s23;
            runxy += sxy - hxy[k];                   hxy[k] = sxy;

            if (r >= 8) {
                float a0, a1, b0, b1;
                upk2(run01, a0, a1);
                upk2(run23, b0, b1);
                __half2 ha = __floats2half2_rn(a0, a1);
                __half2 hb = __floats2half2_rn(b0, b1);
                __half  hc = __float2half_rn(runxy);
                uint2 rec;
                rec.x = *reinterpret_cast<unsigned*>(&ha);
                rec.y = *reinterpret_cast<unsigned*>(&hb);
                const size_t o = obase + (size_t)(hs0 + r - 8) * WW;
                g_scrA[o] = rec;
                g_scrC[o] = *reinterpret_cast<unsigned short*>(&hc);
            }
        }
    }
}

// ================= pass 2 helpers =================
__device__ __forceinline__ float ncc_term(ull runA, ull runB, float rxy) {
    const float invn = 1.0f / 729.0f;
    float sx, sy, sxx, syy;
    upk2(runA, sx, sy);
    upk2(runB, sxx, syy);
    const float xm = sx * invn;
    const float ym = sy * invn;
    const float cross = fmaf(-xm, ym, rxy * invn);
    const float vx    = fmaf(-xm, xm, sxx * invn);
    const float vy    = fmaf(-ym, ym, syy * invn);
    return __fdividef(cross * cross, fmaf(vx, vy, 1e-5f));
}

// ================= pass 2: D sliding + NCC + reduction + finalize ============
__global__ __launch_bounds__(160)
void lncc_pass2(float* __restrict__ out) {
    const int tid = threadIdx.x;         // 0..159
    const int ty  = tid / 80;            // 0..1 -> h row
    const int txp = tid % 80;            // w pair
    const int h   = blockIdx.x * 2 + ty;
    const int dc  = blockIdx.y;
    const int b   = blockIdx.z;
    const int d0  = dc * DS;
    const int w0  = txp * 2;

    const size_t base = (size_t)b * VOLSZ + (size_t)h * WW + w0;

    auto sidx = [&](int jd) -> size_t {
        const int gd = iclamp(d0 - 4 + jd, DD - 1);
        return base + (size_t)gd * (HH * WW);
    };

    // depth-4 prefetch pipeline: one uint4 (2 records' A) + one uint (2 Sxy)
    uint4 pipeA[4];
    unsigned pipeC[4];
    #pragma unroll
    for (int i = 0; i < 4; ++i) {
        const size_t idx = sidx(i);
        pipeA[i] = __ldg(reinterpret_cast<const uint4*>(&g_scrA[idx]));
        pipeC[i] = __ldg(reinterpret_cast<const unsigned*>(&g_scrC[idx]));
    }

    // history as raw fp16 bits (exact add/sub round trip)
    unsigned hA[9][4];
    unsigned hC[9];
    #pragma unroll
    for (int k = 0; k < 9; ++k) {
        hA[k][0] = 0u; hA[k][1] = 0u; hA[k][2] = 0u; hA[k][3] = 0u; hC[k] = 0u;
    }
    ull runA0 = 0ull, runB0 = 0ull, runA1 = 0ull, runB1 = 0ull;
    float runxy0 = 0.f, runxy1 = 0.f;
    float acc = 0.f;

    #pragma unroll
    for (int jd = 0; jd < STEPS; ++jd) {
        const uint4    A = pipeA[jd & 3];
        const unsigned C = pipeC[jd & 3];
        if (jd + 4 < STEPS) {
            const size_t idx = sidx(jd + 4);
            pipeA[jd & 3] = __ldg(reinterpret_cast<const uint4*>(&g_scrA[idx]));
            pipeC[jd & 3] = __ldg(reinterpret_cast<const unsigned*>(&g_scrC[idx]));
        }

        const int k = jd % 9;
        // column 0
        {
            const float2 a  = h2f(A.x);
            const float2 q  = h2f(A.y);
            const float2 oa = h2f(hA[k][0]);
            const float2 oq = h2f(hA[k][1]);
            runA0 = add2(runA0, sub2(pk2(a.x, a.y), pk2(oa.x, oa.y)));
            runB0 = add2(runB0, sub2(pk2(q.x, q.y), pk2(oq.x, oq.y)));
        }
        // column 1
        {
            const float2 a  = h2f(A.z);
            const float2 q  = h2f(A.w);
            const float2 oa = h2f(hA[k][2]);
            const float2 oq = h2f(hA[k][3]);
            runA1 = add2(runA1, sub2(pk2(a.x, a.y), pk2(oa.x, oa.y)));
            runB1 = add2(runB1, sub2(pk2(q.x, q.y), pk2(oq.x, oq.y)));
        }
        // Sxy for both columns (packed half2)
        {
            const float2 c  = h2f(C);
            const float2 oc = h2f(hC[k]);
            runxy0 += c.x - oc.x;
            runxy1 += c.y - oc.y;
        }
        hA[k][0] = A.x; hA[k][1] = A.y; hA[k][2] = A.z; hA[k][3] = A.w; hC[k] = C;

        if (jd >= 8) {
            acc += ncc_term(runA0, runB0, runxy0);
            acc += ncc_term(runA1, runB1, runxy1);
        }
    }

    // block reduce (5 warps) -> double atomic -> fused finalize
    __shared__ float red[5];
    #pragma unroll
    for (int o = 16; o > 0; o >>= 1)
        acc += __shfl_down_sync(0xffffffffu, acc, o);
    const int warp = tid >> 5;
    const int lane = tid & 31;
    if (lane == 0) red[warp] = acc;
    __syncthreads();
    if (warp == 0 && lane == 0) {
        float v = red[0] + red[1] + red[2] + red[3] + red[4];
        atomicAdd(&g_acc, (double)v);
        __threadfence();
        const unsigned ticket = atomicAdd(&g_ctr, 1u);
        if (ticket == (unsigned)(P2_BLOCKS - 1)) {
            double total = atomicAdd(&g_acc, 0.0);   // ordered read
            out[0] = (float)(-total * (1.0 / (double)VOL2));
        }
    }
}

extern "C" void kernel_launch(void* const* d_in, const int* in_sizes, int n_in,
                              void* d_out, int out_size) {
    (void)in_sizes; (void)n_in; (void)out_size;
    const float* x = (const float*)d_in[0];
    const float* y = (const float*)d_in[1];
    float* out = (float*)d_out;

    dim3 g1(NH, DD, BB);          // 4 x 160 x 2 = 1280 blocks, 160 thr
    lncc_pass1<<<g1, WW>>>(x, y);

    dim3 g2(HH / 2, ND, BB);      // 80 x 4 x 2 = 640 blocks, 160 thr
    lncc_pass2<<<g2, 160>>>(out);
}

// round 8
// speedup vs baseline: 2.8829x; 1.2476x over previous
#include <cuda_runtime.h>
#include <cuda_fp16.h>

// LNCC loss, two-pass separable:
//   pass1: block = 2 d-planes x 80 w-pairs. cp.async 8-row ring, 2 rows per
//          barrier. Each thread computes TWO adjacent 9-tap W sums (shared
//          taps, 5 LDS.128), slides them down H with an fp16-bit register
//          history (exact add/sub), stores 10 B/voxel fp16 scratch.
//   pass2: thread owns 2 adjacent w cols; one LDG.128+LDG.32 lead (depth-4
//          prefetch) and one L1-hit trail reload (jd-9) per D-step -> no
//          history registers. NCC + fused reduction/finalize.

#define BB 2
#define DD 160
#define HH 160
#define WW 160
#define VOLSZ (DD*HH*WW)
#define VOL2  (BB*VOLSZ)

#define NH 4
#define HS (HH/NH)          // 40 output rows per block
#define ROWS (HS + 8)       // 48 row steps

#define ND 4
#define DS (DD/ND)          // 40
#define STEPS (DS + 8)      // 48

#define P2_BLOCKS ((HH/2) * ND * BB)   // 640

__device__ __align__(16) uint2          g_scrA[VOL2];   // {half2(Sx,Sy), half2(Sxx,Syy)}
__device__ __align__(16) unsigned short g_scrC[VOL2];   // half(Sxy)
__device__ double g_acc;
__device__ unsigned int g_ctr;

// ---- packed f32x2 helpers (sm_100+) ----
typedef unsigned long long ull;
__device__ __forceinline__ ull pk2(float a, float b) {
    ull r; asm("mov.b64 %0, {%1, %2};" : "=l"(r) : "f"(a), "f"(b)); return r;
}
__device__ __forceinline__ void upk2(ull v, float& a, float& b) {
    asm("mov.b64 {%0, %1}, %2;" : "=f"(a), "=f"(b) : "l"(v));
}
__device__ __forceinline__ ull add2(ull a, ull b) {
    ull d; asm("add.rn.f32x2 %0, %1, %2;" : "=l"(d) : "l"(a), "l"(b)); return d;
}
__device__ __forceinline__ ull sub2(ull a, ull b) {
    ull d; asm("sub.rn.f32x2 %0, %1, %2;" : "=l"(d) : "l"(a), "l"(b)); return d;
}
__device__ __forceinline__ ull mul2(ull a, ull b) {
    ull d; asm("mul.rn.f32x2 %0, %1, %2;" : "=l"(d) : "l"(a), "l"(b)); return d;
}
__device__ __forceinline__ ull fma2(ull a, ull b, ull c) {
    ull d; asm("fma.rn.f32x2 %0, %1, %2, %3;" : "=l"(d) : "l"(a), "l"(b), "l"(c)); return d;
}

__device__ __forceinline__ int iclamp(int v, int hi) { return min(max(v, 0), hi); }

__device__ __forceinline__ float2 h2f(unsigned bits) {
    __half2 h = *reinterpret_cast<__half2*>(&bits);
    return __half22float2(h);
}
__device__ __forceinline__ unsigned f2hbits(float a, float b) {
    __half2 h = __floats2half2_rn(a, b);
    return *reinterpret_cast<unsigned*>(&h);
}

__device__ __forceinline__ void cpa4(void* dst_smem, const void* src) {
    unsigned s = (unsigned)__cvta_generic_to_shared(dst_smem);
    asm volatile("cp.async.ca.shared.global [%0], [%1], 4;" :: "r"(s), "l"(src));
}
#define CPA_COMMIT() asm volatile("cp.async.commit_group;" ::: "memory")
#define CPA_WAIT4()  asm volatile("cp.async.wait_group 4;" ::: "memory")

// slide one packed field through fp16-bit history (exact add/sub round trip)
__device__ __forceinline__ void slide_p(ull s, unsigned& hist, ull& run) {
    float f0, f1; upk2(s, f0, f1);
    const unsigned nb = f2hbits(f0, f1);
    const float2 nf = h2f(nb);
    const float2 of = h2f(hist);
    run = add2(run, sub2(pk2(nf.x, nf.y), pk2(of.x, of.y)));
    hist = nb;
}
__device__ __forceinline__ unsigned pack_run(ull run) {
    float f0, f1; upk2(run, f0, f1);
    return f2hbits(f0, f1);
}

// ================= pass 1 =================
__global__ __launch_bounds__(160)
void lncc_pass1(const float* __restrict__ x, const float* __restrict__ y) {
    __shared__ __align__(16) float2 buf[2][8][WW + 8];

    const int tid = threadIdx.x;
    const int ty  = tid / 80;            // plane select
    const int txp = tid % 80;            // w pair
    const int w0  = txp * 2;

    const int strip = blockIdx.x;
    const int d     = blockIdx.y * 2 + ty;
    const int b     = blockIdx.z;
    const int hs0   = strip * HS;

    if (blockIdx.x == 0 && blockIdx.y == 0 && blockIdx.z == 0 && tid == 0) {
        g_acc = 0.0;
        g_ctr = 0u;
    }

    const float* xp = x + ((size_t)b * DD + d) * (HH * WW);
    const float* yp = y + ((size_t)b * DD + d) * (HH * WW);

    auto issue = [&](int r) {
        const int gh = iclamp(hs0 - 4 + r, HH - 1);
        const float* xr = xp + gh * WW;
        const float* yr = yp + gh * WW;
        float2* dst = buf[ty][r & 7];
        #pragma unroll
        for (int e0 = 0; e0 < 3; ++e0) {
            const int e = txp + e0 * 80;
            if (e < WW + 8) {
                const int gw = iclamp(e - 4, WW - 1);
                cpa4(&dst[e].x, xr + gw);
                cpa4(&dst[e].y, yr + gw);
            }
        }
        CPA_COMMIT();
    };

    issue(0); issue(1); issue(2); issue(3); issue(4); issue(5);

    // fp16-bit history: per column A=(Sx,Sy), B=(Sxx,Syy); shared XY pair
    unsigned hA0[9], hB0[9], hA1[9], hB1[9], hXY[9];
    #pragma unroll
    for (int k = 0; k < 9; ++k) { hA0[k]=0u; hB0[k]=0u; hA1[k]=0u; hB1[k]=0u; hXY[k]=0u; }
    ull rA0 = 0ull, rB0 = 0ull, rA1 = 0ull, rB1 = 0ull;
    float rxy0 = 0.f, rxy1 = 0.f;

    const size_t obase = ((size_t)b * DD + d) * (HH * WW) + w0;

    #pragma unroll
    for (int it = 0; it < ROWS / 2; ++it) {
        CPA_WAIT4();
        __syncthreads();

        if (2 * it + 6 < ROWS) issue(2 * it + 6); else CPA_COMMIT();
        if (2 * it + 7 < ROWS) issue(2 * it + 7); else CPA_COMMIT();

        #pragma unroll
        for (int sub = 0; sub < 2; ++sub) {
            const int r = 2 * it + sub;
            const float4* row4 = reinterpret_cast<const float4*>(buf[ty][r & 7]);

            // taps e = w0 .. w0+9  (float4 = two (x,y) pairs)
            const float4 q0 = row4[txp];
            const float4 q1 = row4[txp + 1];
            const float4 q2 = row4[txp + 2];
            const float4 q3 = row4[txp + 3];
            const float4 q4 = row4[txp + 4];

            const ull pp0 = pk2(q0.x, q0.y), pp1 = pk2(q0.z, q0.w);
            const ull pp2 = pk2(q1.x, q1.y), pp3 = pk2(q1.z, q1.w);
            const ull pp4 = pk2(q2.x, q2.y), pp5 = pk2(q2.z, q2.w);
            const ull pp6 = pk2(q3.x, q3.y), pp7 = pk2(q3.z, q3.w);
            const ull pp8 = pk2(q4.x, q4.y), pp9 = pk2(q4.z, q4.w);

            // column 0: taps 0..8
            ull s01 = add2(pp0, pp1);
            s01 = add2(s01, pp2); s01 = add2(s01, pp3); s01 = add2(s01, pp4);
            s01 = add2(s01, pp5); s01 = add2(s01, pp6); s01 = add2(s01, pp7);
            s01 = add2(s01, pp8);
            ull s23 = mul2(pp0, pp0);
            s23 = fma2(pp1, pp1, s23); s23 = fma2(pp2, pp2, s23);
            s23 = fma2(pp3, pp3, s23); s23 = fma2(pp4, pp4, s23);
            s23 = fma2(pp5, pp5, s23); s23 = fma2(pp6, pp6, s23);
            s23 = fma2(pp7, pp7, s23); s23 = fma2(pp8, pp8, s23);
            float sxy0 = q0.x * q0.y;
            sxy0 = fmaf(q0.z, q0.w, sxy0); sxy0 = fmaf(q1.x, q1.y, sxy0);
            sxy0 = fmaf(q1.z, q1.w, sxy0); sxy0 = fmaf(q2.x, q2.y, sxy0);
            sxy0 = fmaf(q2.z, q2.w, sxy0); sxy0 = fmaf(q3.x, q3.y, sxy0);
            sxy0 = fmaf(q3.z, q3.w, sxy0); sxy0 = fmaf(q4.x, q4.y, sxy0);

            // column 1: taps 1..9 = col0 - tap0 + tap9
            const ull s01b = add2(sub2(s01, pp0), pp9);
            const ull s23b = fma2(pp9, pp9, sub2(s23, mul2(pp0, pp0)));
            const float sxy1 = fmaf(q4.z, q4.w, fmaf(-q0.x, q0.y, sxy0));

            const int k = r % 9;   // static per unrolled iteration
            slide_p(s01,  hA0[k], rA0);
            slide_p(s23,  hB0[k], rB0);
            slide_p(s01b, hA1[k], rA1);
            slide_p(s23b, hB1[k], rB1);
            {
                const unsigned nb = f2hbits(sxy0, sxy1);
                const float2 nf = h2f(nb);
                const float2 of = h2f(hXY[k]);
                rxy0 += nf.x - of.x;
                rxy1 += nf.y - of.y;
                hXY[k] = nb;
            }

            if (r >= 8) {
                uint4 rec;
                rec.x = pack_run(rA0);
                rec.y = pack_run(rB0);
                rec.z = pack_run(rA1);
                rec.w = pack_run(rB1);
                const size_t o = obase + (size_t)(hs0 + r - 8) * WW;
                *reinterpret_cast<uint4*>(&g_scrA[o]) = rec;
                *reinterpret_cast<unsigned*>(&g_scrC[o]) = f2hbits(rxy0, rxy1);
            }
        }
    }
}

// ================= pass 2 helpers =================
__device__ __forceinline__ float ncc_term(ull runA, ull runB, float rxy) {
    const float invn = 1.0f / 729.0f;
    float sx, sy, sxx, syy;
    upk2(runA, sx, sy);
    upk2(runB, sxx, syy);
    const float xm = sx * invn;
    const float ym = sy * invn;
    const float cross = fmaf(-xm, ym, rxy * invn);
    const float vx    = fmaf(-xm, xm, sxx * invn);
    const float vy    = fmaf(-ym, ym, syy * invn);
    return __fdividef(cross * cross, fmaf(vx, vy, 1e-5f));
}

// ================= pass 2: D sliding + NCC + reduction + finalize ============
__global__ __launch_bounds__(160)
void lncc_pass2(float* __restrict__ out) {
    const int tid = threadIdx.x;         // 0..159
    const int ty  = tid / 80;            // h row
    const int txp = tid % 80;            // w pair
    const int h   = blockIdx.x * 2 + ty;
    const int dc  = blockIdx.y;
    const int b   = blockIdx.z;
    const int d0  = dc * DS;
    const int w0  = txp * 2;

    const size_t base = (size_t)b * VOLSZ + (size_t)h * WW + w0;

    auto sidx = [&](int jd) -> size_t {
        const int gd = iclamp(d0 - 4 + jd, DD - 1);
        return base + (size_t)gd * (HH * WW);
    };

    // depth-4 lead prefetch: one uint4 (2 records' A) + one uint (2 Sxy)
    uint4 pipeA[4];
    unsigned pipeC[4];
    #pragma unroll
    for (int i = 0; i < 4; ++i) {
        const size_t idx = sidx(i);
        pipeA[i] = __ldg(reinterpret_cast<const uint4*>(&g_scrA[idx]));
        pipeC[i] = __ldg(reinterpret_cast<const unsigned*>(&g_scrC[idx]));
    }

    ull runA0 = 0ull, runB0 = 0ull, runA1 = 0ull, runB1 = 0ull;
    float runxy0 = 0.f, runxy1 = 0.f;
    float acc = 0.f;

    auto consume = [&](int jd, bool trail, bool emit) {
        const uint4    A = pipeA[jd & 3];
        const unsigned C = pipeC[jd & 3];
        if (jd + 4 < STEPS) {
            const size_t idx = sidx(jd + 4);
            pipeA[jd & 3] = __ldg(reinterpret_cast<const uint4*>(&g_scrA[idx]));
            pipeC[jd & 3] = __ldg(reinterpret_cast<const unsigned*>(&g_scrC[idx]));
        }
        uint4 T = make_uint4(0u, 0u, 0u, 0u);
        unsigned Tc = 0u;
        if (trail) {                      // record from step jd-9: L1 hit
            const size_t idx = sidx(jd - 9);
            T  = __ldg(reinterpret_cast<const uint4*>(&g_scrA[idx]));
            Tc = __ldg(reinterpret_cast<const unsigned*>(&g_scrC[idx]));
        }
        {
            const float2 a = h2f(A.x), oa = h2f(T.x);
            const float2 q = h2f(A.y), oq = h2f(T.y);
            runA0 = add2(runA0, sub2(pk2(a.x, a.y), pk2(oa.x, oa.y)));
            runB0 = add2(runB0, sub2(pk2(q.x, q.y), pk2(oq.x, oq.y)));
        }
        {
            const float2 a = h2f(A.z), oa = h2f(T.z);
            const float2 q = h2f(A.w), oq = h2f(T.w);
            runA1 = add2(runA1, sub2(pk2(a.x, a.y), pk2(oa.x, oa.y)));
            runB1 = add2(runB1, sub2(pk2(q.x, q.y), pk2(oq.x, oq.y)));
        }
        {
            const float2 c = h2f(C), oc = h2f(Tc);
            runxy0 += c.x - oc.x;
            runxy1 += c.y - oc.y;
        }
        if (emit) {
            acc += ncc_term(runA0, runB0, runxy0);
            acc += ncc_term(runA1, runB1, runxy1);
        }
    };

    #pragma unroll
    for (int jd = 0; jd < 8; ++jd) consume(jd, false, false);
    consume(8, false, true);
    #pragma unroll 8
    for (int jd = 9; jd < STEPS; ++jd) consume(jd, true, true);

    // block reduce (5 warps) -> double atomic -> fused finalize
    __shared__ float red[5];
    #pragma unroll
    for (int o = 16; o > 0; o >>= 1)
        acc += __shfl_down_sync(0xffffffffu, acc, o);
    const int warp = tid >> 5;
    const int lane = tid & 31;
    if (lane == 0) red[warp] = acc;
    __syncthreads();
    if (warp == 0 && lane == 0) {
        float v = red[0] + red[1] + red[2] + red[3] + red[4];
        atomicAdd(&g_acc, (double)v);
        __threadfence();
        const unsigned ticket = atomicAdd(&g_ctr, 1u);
        if (ticket == (unsigned)(P2_BLOCKS - 1)) {
            double total = atomicAdd(&g_acc, 0.0);   // ordered read
            out[0] = (float)(-total * (1.0 / (double)VOL2));
        }
    }
}

extern "C" void kernel_launch(void* const* d_in, const int* in_sizes, int n_in,
                              void* d_out, int out_size) {
    (void)in_sizes; (void)n_in; (void)out_size;
    const float* x = (const float*)d_in[0];
    const float* y = (const float*)d_in[1];
    float* out = (float*)d_out;

    dim3 g1(NH, DD / 2, BB);      // 4 x 80 x 2 = 640 blocks, 160 thr
    lncc_pass1<<<g1, 160>>>(x, y);

    dim3 g2(HH / 2, ND, BB);      // 80 x 4 x 2 = 640 blocks, 160 thr
    lncc_pass2<<<g2, 160>>>(out);
}